// round 1
// baseline (speedup 1.0000x reference)
#include <cuda_runtime.h>
#include <math.h>

#define KK     15
#define HALO   7
#define TS     32
#define XS_ROWS 46          // TS + 2*HALO
#define SROW   49           // padded row stride (conflict-free)
#define NF     48           // SO*2 filters
#define NSO    24
#define HW     128
#define PLANE  16384        // 128*128
#define CIN    768          // C*SO

static const int SMEM_A = (225 * NF + XS_ROWS * SROW) * 4;   // 43200 + 9016 = 52216 B
static const int SMEM_B = CIN * 32 * 4;                      // 98304 B

// Scratch (zero-init .bss; no runtime allocation)
__device__ float g_mag[(size_t)4 * CIN * PLANE];   // 201 MB: [b][c*24+so][q], q in conv coords
__device__ float g_z[(size_t)128 * PLANE];         // 8 MB:   [b*32+o][q]
__device__ float g_stats[256];                     // per-plane mean, rstd

// ---------------------------------------------------------------------------
// Kernel A: depthwise Gabor conv (cross-correlation, zero pad 7) + magnitude
// grid (16 tiles, 128 planes), 256 threads; thread = 4 px along x, 12 filters/pass
// ---------------------------------------------------------------------------
__global__ __launch_bounds__(256, 2)
void gabor_kernel(const float* __restrict__ x, const float* __restrict__ filters) {
    extern __shared__ float sm[];
    float* fs = sm;                 // [225][48] : fs[tap*48 + (so*2+ri)]
    float* xs = sm + 225 * NF;      // [46][49]

    const int tid   = threadIdx.x;
    const int plane = blockIdx.y;           // b*32 + c
    const int tile  = blockIdx.x;
    const int ty0   = (tile >> 2) * TS;
    const int tx0   = (tile & 3) * TS;

    // stage filters, transposed to [tap][f]
    for (int i = tid; i < 225 * NF; i += 256) {
        int tap = i / NF, f = i - tap * NF;
        fs[i] = filters[(f >> 1) * 450 + (f & 1) * 225 + tap];
    }
    // stage x tile + halo (zero padded)
    const float* xp = x + (size_t)plane * PLANE;
    const int gy0 = ty0 - HALO, gx0 = tx0 - HALO;
    for (int i = tid; i < XS_ROWS * XS_ROWS; i += 256) {
        int r = i / XS_ROWS, c = i - r * XS_ROWS;
        int gy = gy0 + r, gx = gx0 + c;
        float v = 0.f;
        if (gy >= 0 && gy < HW && gx >= 0 && gx < HW) v = xp[gy * HW + gx];
        xs[r * SROW + c] = v;
    }
    __syncthreads();

    const int x0 = (tid & 7) * 4;    // 4 consecutive px along x
    const int ry = tid >> 3;         // row within tile
    const int b  = plane >> 5, c = plane & 31;
    const size_t mbase0 = ((size_t)b * CIN + (size_t)c * NSO) * PLANE
                        + (size_t)(ty0 + ry) * HW + tx0 + x0;

    for (int g = 0; g < 4; ++g) {    // 4 passes x 6 complex filters
        float acc[4][12];
#pragma unroll
        for (int p = 0; p < 4; ++p)
#pragma unroll
            for (int f = 0; f < 12; ++f) acc[p][f] = 0.f;

        for (int dy = 0; dy < KK; ++dy) {
            const float* xr = xs + (ry + dy) * SROW + x0;
            const float* wr = fs + dy * KK * NF + g * 12;
#pragma unroll
            for (int dx = 0; dx < KK; ++dx) {
                float wv[12];
                *(float4*)(wv)     = *(const float4*)(wr + dx * NF);
                *(float4*)(wv + 4) = *(const float4*)(wr + dx * NF + 4);
                *(float4*)(wv + 8) = *(const float4*)(wr + dx * NF + 8);
                float xv[4];
#pragma unroll
                for (int p = 0; p < 4; ++p) xv[p] = xr[dx + p];
#pragma unroll
                for (int p = 0; p < 4; ++p)
#pragma unroll
                    for (int f = 0; f < 12; ++f)
                        acc[p][f] = fmaf(xv[p], wv[f], acc[p][f]);
            }
        }
        // magnitude + coalesced float4 store (conv-natural layout)
#pragma unroll
        for (int s = 0; s < 6; ++s) {
            float4 m;
            m.x = sqrtf(acc[0][2*s] * acc[0][2*s] + acc[0][2*s+1] * acc[0][2*s+1]);
            m.y = sqrtf(acc[1][2*s] * acc[1][2*s] + acc[1][2*s+1] * acc[1][2*s+1]);
            m.z = sqrtf(acc[2][2*s] * acc[2][2*s] + acc[2][2*s+1] * acc[2][2*s+1]);
            m.w = sqrtf(acc[3][2*s] * acc[3][2*s] + acc[3][2*s+1] * acc[3][2*s+1]);
            int so = g * 6 + s;
            *(float4*)(g_mag + mbase0 + (size_t)so * PLANE) = m;
        }
    }
}

// ---------------------------------------------------------------------------
// Kernel B: z[b,o,q] = sum_j w1[o,j] * mag[b,j,q]   (bias dropped: cancels in IN)
// grid (32 q-blocks, 4 batches), 256 threads, 2 q per thread
// ---------------------------------------------------------------------------
__global__ __launch_bounds__(256, 2)
void mix_kernel(const float* __restrict__ w1) {
    extern __shared__ float w1s[];   // [768][32] transposed
    const int tid = threadIdx.x;
    for (int i = tid; i < CIN * 32; i += 256) {
        int j = i >> 5, o = i & 31;
        w1s[i] = w1[o * CIN + j];
    }
    __syncthreads();

    const int bb = blockIdx.y;
    const int q0 = blockIdx.x * 512 + tid * 2;
    const float* mp = g_mag + (size_t)bb * CIN * PLANE + q0;

    float acc0[32], acc1[32];
#pragma unroll
    for (int o = 0; o < 32; ++o) { acc0[o] = 0.f; acc1[o] = 0.f; }

#pragma unroll 4
    for (int j = 0; j < CIN; ++j) {
        float2 m = *(const float2*)(mp + (size_t)j * PLANE);
        const float4* wrow = (const float4*)(w1s + j * 32);
#pragma unroll
        for (int o4 = 0; o4 < 8; ++o4) {
            float4 w = wrow[o4];
            acc0[o4*4+0] = fmaf(m.x, w.x, acc0[o4*4+0]);
            acc1[o4*4+0] = fmaf(m.y, w.x, acc1[o4*4+0]);
            acc0[o4*4+1] = fmaf(m.x, w.y, acc0[o4*4+1]);
            acc1[o4*4+1] = fmaf(m.y, w.y, acc1[o4*4+1]);
            acc0[o4*4+2] = fmaf(m.x, w.z, acc0[o4*4+2]);
            acc1[o4*4+2] = fmaf(m.y, w.z, acc1[o4*4+2]);
            acc0[o4*4+3] = fmaf(m.x, w.w, acc0[o4*4+3]);
            acc1[o4*4+3] = fmaf(m.y, w.w, acc1[o4*4+3]);
        }
    }
#pragma unroll
    for (int o = 0; o < 32; ++o) {
        float2 v = make_float2(acc0[o], acc1[o]);
        *(float2*)(g_z + (size_t)(bb * 32 + o) * PLANE + q0) = v;
    }
}

// ---------------------------------------------------------------------------
// Kernel C: per-plane mean / rstd (deterministic tree reduction)
// ---------------------------------------------------------------------------
__global__ void stats_kernel() {
    const int plane = blockIdx.x;
    const float* zp = g_z + (size_t)plane * PLANE;
    const int tid = threadIdx.x;
    float s = 0.f, s2 = 0.f;
    for (int i = tid * 4; i < PLANE; i += 1024) {
        float4 v = *(const float4*)(zp + i);
        s  += v.x + v.y + v.z + v.w;
        s2 += v.x * v.x + v.y * v.y + v.z * v.z + v.w * v.w;
    }
    __shared__ float r1[256], r2[256];
    r1[tid] = s; r2[tid] = s2;
    __syncthreads();
    for (int st = 128; st > 0; st >>= 1) {
        if (tid < st) { r1[tid] += r1[tid + st]; r2[tid] += r2[tid + st]; }
        __syncthreads();
    }
    if (tid == 0) {
        float mean = r1[0] * (1.f / PLANE);
        float var  = r2[0] * (1.f / PLANE) - mean * mean;
        g_stats[plane * 2]     = mean;
        g_stats[plane * 2 + 1] = rsqrtf(var + 1e-5f);
    }
}

// ---------------------------------------------------------------------------
// Kernel D: normalize + H<->W transpose via smem tile
// out[b,o,h,w] = (z[b,o, w*128+h] - mean) * rstd
// ---------------------------------------------------------------------------
__global__ void norm_kernel(float* __restrict__ out) {
    __shared__ float s[32][33];
    const int plane = blockIdx.y;
    const int tile  = blockIdx.x;
    const int hb = (tile >> 2) * 32, wb = (tile & 3) * 32;
    const float mean = g_stats[plane * 2];
    const float rstd = g_stats[plane * 2 + 1];
    const float* zp = g_z + (size_t)plane * PLANE;
    float* op = out + (size_t)plane * PLANE;
    const int cc = threadIdx.x & 31;
    const int r0 = threadIdx.x >> 5;   // 0..7
#pragma unroll
    for (int k = 0; k < 4; ++k) {
        int rr = r0 + k * 8;
        s[rr][cc] = zp[(wb + rr) * HW + hb + cc];
    }
    __syncthreads();
#pragma unroll
    for (int k = 0; k < 4; ++k) {
        int rr = r0 + k * 8;
        op[(hb + rr) * HW + wb + cc] = (s[cc][rr] - mean) * rstd;
    }
}

// ---------------------------------------------------------------------------
extern "C" void kernel_launch(void* const* d_in, const int* in_sizes, int n_in,
                              void* d_out, int out_size) {
    const float* x       = (const float*)d_in[0];   // (4,32,128,128)
    const float* filters = (const float*)d_in[1];   // (24,2,15,15)
    const float* w1      = (const float*)d_in[2];   // (32,768)
    // d_in[3] = b1 : cancels under instance-norm mean subtraction — unused
    float* out = (float*)d_out;

    cudaFuncSetAttribute(gabor_kernel, cudaFuncAttributeMaxDynamicSharedMemorySize, SMEM_A);
    cudaFuncSetAttribute(mix_kernel,   cudaFuncAttributeMaxDynamicSharedMemorySize, SMEM_B);

    gabor_kernel<<<dim3(16, 128), 256, SMEM_A>>>(x, filters);
    mix_kernel<<<dim3(32, 4), 256, SMEM_B>>>(w1);
    stats_kernel<<<128, 256>>>();
    norm_kernel<<<dim3(16, 128), 256>>>(out);
}

// round 2
// speedup vs baseline: 1.2444x; 1.2444x over previous
#include <cuda_runtime.h>
#include <math.h>

#define KK     15
#define HALO   7
#define TS     32
#define XS_ROWS 46          // TS + 2*HALO
#define SROW   49           // padded row stride (conflict-free)
#define NF     48           // SO*2 filters
#define NSO    24
#define HW     128
#define PLANE  16384        // 128*128
#define CIN    768          // C*SO

static const int SMEM_A = (225 * NF + XS_ROWS * SROW) * 4;   // 43200 + 9016 = 52216 B
static const int SMEM_B = CIN * 32 * 4;                      // 98304 B

typedef unsigned long long u64;

// Scratch (zero-init .bss; no runtime allocation)
__device__ float g_mag[(size_t)4 * CIN * PLANE];   // 201 MB: [b][c*24+so][q], q in conv coords
__device__ float g_z[(size_t)128 * PLANE];         // 8 MB:   [b*32+o][q]
__device__ float g_stats[256];                     // per-plane mean, rstd

// ---- packed f32x2 helpers (sm_103a) ---------------------------------------
__device__ __forceinline__ u64 pk2(float lo, float hi) {
    u64 r; asm("mov.b64 %0, {%1,%2};" : "=l"(r) : "f"(lo), "f"(hi)); return r;
}
__device__ __forceinline__ u64 splat(float v) {
    u64 r; asm("mov.b64 %0, {%1,%1};" : "=l"(r) : "f"(v)); return r;
}
__device__ __forceinline__ void fma2(u64& d, u64 a, u64 b) {
    asm("fma.rn.f32x2 %0, %1, %2, %0;" : "+l"(d) : "l"(a), "l"(b));
}
__device__ __forceinline__ void upk2(u64 v, float& lo, float& hi) {
    asm("mov.b64 {%0,%1}, %2;" : "=f"(lo), "=f"(hi) : "l"(v));
}

// ---------------------------------------------------------------------------
// Kernel A: depthwise Gabor conv (cross-correlation, zero pad 7) + magnitude.
// FFMA2 form: filter (re,im) pairs packed in b64, pixel splatted.
// grid (16 tiles, 128 planes), 256 threads; thread = 4 px along x, 6 complex/pass
// ---------------------------------------------------------------------------
__global__ __launch_bounds__(256, 2)
void gabor_kernel(const float* __restrict__ x, const float* __restrict__ filters) {
    extern __shared__ float sm[];
    float* fs = sm;                 // [225][48] : fs[tap*48 + (so*2+ri)]
    float* xs = sm + 225 * NF;      // [46][49]

    const int tid   = threadIdx.x;
    const int plane = blockIdx.y;           // b*32 + c
    const int tile  = blockIdx.x;
    const int ty0   = (tile >> 2) * TS;
    const int tx0   = (tile & 3) * TS;

    // stage filters, transposed to [tap][f]; f = so*2 + (re/im)
    for (int i = tid; i < 225 * NF; i += 256) {
        int tap = i / NF, f = i - tap * NF;
        fs[i] = filters[(f >> 1) * 450 + (f & 1) * 225 + tap];
    }
    // stage x tile + halo (zero padded)
    const float* xp = x + (size_t)plane * PLANE;
    const int gy0 = ty0 - HALO, gx0 = tx0 - HALO;
    for (int i = tid; i < XS_ROWS * XS_ROWS; i += 256) {
        int r = i / XS_ROWS, c = i - r * XS_ROWS;
        int gy = gy0 + r, gx = gx0 + c;
        float v = 0.f;
        if (gy >= 0 && gy < HW && gx >= 0 && gx < HW) v = xp[gy * HW + gx];
        xs[r * SROW + c] = v;
    }
    __syncthreads();

    const int x0 = (tid & 7) * 4;    // 4 consecutive px along x
    const int ry = tid >> 3;         // row within tile
    const int b  = plane >> 5, c = plane & 31;
    const size_t mbase0 = ((size_t)b * CIN + (size_t)c * NSO) * PLANE
                        + (size_t)(ty0 + ry) * HW + tx0 + x0;

    for (int g = 0; g < 4; ++g) {    // 4 passes x 6 complex filters
        u64 acc[4][6];               // [pixel][complex filter] packed (re,im)
#pragma unroll
        for (int p = 0; p < 4; ++p)
#pragma unroll
            for (int s = 0; s < 6; ++s) acc[p][s] = 0ull;

        for (int dy = 0; dy < KK; ++dy) {
            const float* xr = xs + (ry + dy) * SROW + x0;
            const float* wr = fs + dy * KK * NF + g * 12;
#pragma unroll
            for (int dx = 0; dx < KK; ++dx) {
                // 12 filter floats = 6 packed (re,im) pairs; 16B-aligned
                const float* w = wr + dx * NF;
                ulonglong2 wa = *(const ulonglong2*)(w);
                ulonglong2 wb = *(const ulonglong2*)(w + 4);
                ulonglong2 wc = *(const ulonglong2*)(w + 8);
                u64 wp[6] = {wa.x, wa.y, wb.x, wb.y, wc.x, wc.y};
                u64 xv[4];
#pragma unroll
                for (int p = 0; p < 4; ++p) xv[p] = splat(xr[dx + p]);
#pragma unroll
                for (int p = 0; p < 4; ++p)
#pragma unroll
                    for (int s = 0; s < 6; ++s)
                        fma2(acc[p][s], xv[p], wp[s]);
            }
        }
        // magnitude + coalesced float4 store (conv-natural layout)
#pragma unroll
        for (int s = 0; s < 6; ++s) {
            float re[4], im[4];
#pragma unroll
            for (int p = 0; p < 4; ++p) upk2(acc[p][s], re[p], im[p]);
            float4 m;
            m.x = sqrtf(re[0] * re[0] + im[0] * im[0]);
            m.y = sqrtf(re[1] * re[1] + im[1] * im[1]);
            m.z = sqrtf(re[2] * re[2] + im[2] * im[2]);
            m.w = sqrtf(re[3] * re[3] + im[3] * im[3]);
            int so = g * 6 + s;
            *(float4*)(g_mag + mbase0 + (size_t)so * PLANE) = m;
        }
    }
}

// ---------------------------------------------------------------------------
// Kernel B: z[b,o,q] = sum_j w1[o,j] * mag[b,j,q]   (bias dropped: cancels in IN)
// FFMA2 form: output-channel pairs packed, mag value splatted.
// grid (32 q-blocks, 4 batches), 256 threads, 2 q per thread
// ---------------------------------------------------------------------------
__global__ __launch_bounds__(256, 2)
void mix_kernel(const float* __restrict__ w1) {
    extern __shared__ float w1s[];   // [768][32] transposed: w1s[j*32+o]
    const int tid = threadIdx.x;
    for (int i = tid; i < CIN * 32; i += 256) {
        int j = i >> 5, o = i & 31;
        w1s[i] = w1[o * CIN + j];
    }
    __syncthreads();

    const int bb = blockIdx.y;
    const int q0 = blockIdx.x * 512 + tid * 2;
    const float* mp = g_mag + (size_t)bb * CIN * PLANE + q0;

    u64 acc[16][2];   // [o-pair][q]
#pragma unroll
    for (int op = 0; op < 16; ++op) { acc[op][0] = 0ull; acc[op][1] = 0ull; }

#pragma unroll 4
    for (int j = 0; j < CIN; ++j) {
        float2 m = *(const float2*)(mp + (size_t)j * PLANE);
        u64 mx = splat(m.x), my = splat(m.y);
        const ulonglong2* wrow = (const ulonglong2*)(w1s + j * 32);
#pragma unroll
        for (int q4 = 0; q4 < 8; ++q4) {
            ulonglong2 w2 = wrow[q4];
            fma2(acc[q4 * 2 + 0][0], mx, w2.x);
            fma2(acc[q4 * 2 + 0][1], my, w2.x);
            fma2(acc[q4 * 2 + 1][0], mx, w2.y);
            fma2(acc[q4 * 2 + 1][1], my, w2.y);
        }
    }
#pragma unroll
    for (int op = 0; op < 16; ++op) {
        float a0lo, a0hi, a1lo, a1hi;
        upk2(acc[op][0], a0lo, a0hi);   // q0: o=2op, o=2op+1
        upk2(acc[op][1], a1lo, a1hi);   // q0+1
        *(float2*)(g_z + (size_t)(bb * 32 + 2 * op)     * PLANE + q0) = make_float2(a0lo, a1lo);
        *(float2*)(g_z + (size_t)(bb * 32 + 2 * op + 1) * PLANE + q0) = make_float2(a0hi, a1hi);
    }
}

// ---------------------------------------------------------------------------
// Kernel C: per-plane mean / rstd (deterministic tree reduction)
// ---------------------------------------------------------------------------
__global__ void stats_kernel() {
    const int plane = blockIdx.x;
    const float* zp = g_z + (size_t)plane * PLANE;
    const int tid = threadIdx.x;
    float s = 0.f, s2 = 0.f;
    for (int i = tid * 4; i < PLANE; i += 1024) {
        float4 v = *(const float4*)(zp + i);
        s  += v.x + v.y + v.z + v.w;
        s2 += v.x * v.x + v.y * v.y + v.z * v.z + v.w * v.w;
    }
    __shared__ float r1[256], r2[256];
    r1[tid] = s; r2[tid] = s2;
    __syncthreads();
    for (int st = 128; st > 0; st >>= 1) {
        if (tid < st) { r1[tid] += r1[tid + st]; r2[tid] += r2[tid + st]; }
        __syncthreads();
    }
    if (tid == 0) {
        float mean = r1[0] * (1.f / PLANE);
        float var  = r2[0] * (1.f / PLANE) - mean * mean;
        g_stats[plane * 2]     = mean;
        g_stats[plane * 2 + 1] = rsqrtf(var + 1e-5f);
    }
}

// ---------------------------------------------------------------------------
// Kernel D: normalize + H<->W transpose via smem tile
// out[b,o,h,w] = (z[b,o, w*128+h] - mean) * rstd
// ---------------------------------------------------------------------------
__global__ void norm_kernel(float* __restrict__ out) {
    __shared__ float s[32][33];
    const int plane = blockIdx.y;
    const int tile  = blockIdx.x;
    const int hb = (tile >> 2) * 32, wb = (tile & 3) * 32;
    const float mean = g_stats[plane * 2];
    const float rstd = g_stats[plane * 2 + 1];
    const float* zp = g_z + (size_t)plane * PLANE;
    float* op = out + (size_t)plane * PLANE;
    const int cc = threadIdx.x & 31;
    const int r0 = threadIdx.x >> 5;   // 0..7
#pragma unroll
    for (int k = 0; k < 4; ++k) {
        int rr = r0 + k * 8;
        s[rr][cc] = zp[(wb + rr) * HW + hb + cc];
    }
    __syncthreads();
#pragma unroll
    for (int k = 0; k < 4; ++k) {
        int rr = r0 + k * 8;
        op[(hb + rr) * HW + wb + cc] = (s[cc][rr] - mean) * rstd;
    }
}

// ---------------------------------------------------------------------------
extern "C" void kernel_launch(void* const* d_in, const int* in_sizes, int n_in,
                              void* d_out, int out_size) {
    const float* x       = (const float*)d_in[0];   // (4,32,128,128)
    const float* filters = (const float*)d_in[1];   // (24,2,15,15)
    const float* w1      = (const float*)d_in[2];   // (32,768)
    // d_in[3] = b1 : cancels under instance-norm mean subtraction — unused
    float* out = (float*)d_out;

    cudaFuncSetAttribute(gabor_kernel, cudaFuncAttributeMaxDynamicSharedMemorySize, SMEM_A);
    cudaFuncSetAttribute(mix_kernel,   cudaFuncAttributeMaxDynamicSharedMemorySize, SMEM_B);

    gabor_kernel<<<dim3(16, 128), 256, SMEM_A>>>(x, filters);
    mix_kernel<<<dim3(32, 4), 256, SMEM_B>>>(w1);
    stats_kernel<<<128, 256>>>();
    norm_kernel<<<dim3(16, 128), 256>>>(out);
}